// round 3
// baseline (speedup 1.0000x reference)
#include <cuda_runtime.h>
#include <math.h>

#define Bz 64
#define Sz 128
#define Hz 1024
#define Az 512
#define Vz 32001
#define Tz 32
#define G4 4096

// ---------------- scratch (static device globals; no allocation) ----------------
__device__ float g_Xg[(size_t)Sz * Bz * G4];    // [t][b][4H]  precomputed x@Wih_e^T + b_e
__device__ float g_enc[(size_t)Sz * Bz * Hz];   // [t][b][H]   encoder hidden states
__device__ float g_s1[(size_t)Sz * Bz * Az];    // [s][b][A]   enc@We^T + be
__device__ float g_h[Bz * Hz];
__device__ float g_c[Bz * Hz];
__device__ float g_gates[Bz * G4];
__device__ float g_gates2[Bz * G4];
__device__ float g_dconst[Bz * G4];             // hN@Whh_d^T + b_d  (step-invariant)
__device__ float g_hd[Bz * Hz];
__device__ float g_s2[Bz * Az];
__device__ float g_ctx[Bz * Hz];
__device__ float g_be[G4];
__device__ float g_bd[G4];
__device__ int   g_tok[Bz];
__device__ int   g_is64[2];

__device__ __forceinline__ float sigm(float x) { return 1.0f / (1.0f + expf(-x)); }

// ---------------- int64-vs-int32 detection (device-side, deterministic) ----------
__global__ void k_detect(const int* __restrict__ enc_tok, const int* __restrict__ dec_tok) {
    __shared__ int f0, f1;
    if (threadIdx.x == 0) { f0 = 0; f1 = 0; }
    __syncthreads();
    // If stored as int64 (values < 2^31), the odd 32-bit words are all 0.
    for (int i = threadIdx.x; i < Bz * Sz / 2; i += blockDim.x)
        if (enc_tok[2 * i + 1] != 0) atomicOr(&f0, 1);
    for (int i = threadIdx.x; i < Bz / 2; i += blockDim.x)
        if (dec_tok[2 * i + 1] != 0) atomicOr(&f1, 1);
    __syncthreads();
    if (threadIdx.x == 0) { g_is64[0] = f0 ? 0 : 1; g_is64[1] = f1 ? 0 : 1; }
}

// ---------------- init: biases, h0/c0, initial context, initial tokens ------------
__global__ void k_init(const float* __restrict__ bih_e, const float* __restrict__ bhh_e,
                       const float* __restrict__ bih_d, const float* __restrict__ bhh_d,
                       const float* __restrict__ init_ctx, const int* __restrict__ dec_tok) {
    int i = blockIdx.x * blockDim.x + threadIdx.x;
    if (i < G4) { g_be[i] = bih_e[i] + bhh_e[i]; g_bd[i] = bih_d[i] + bhh_d[i]; }
    if (i < Bz * Hz) { g_h[i] = 0.0f; g_c[i] = 0.0f; g_ctx[i] = init_ctx[i]; }
    if (i < Bz) g_tok[i] = g_is64[1] ? dec_tok[2 * i] : dec_tok[i];
}

// ---------------- generic tiled NT GEMM: out = A[MxK] * W[NxK]^T -----------------
// BM=64, BN=64, BK=16, 256 threads, 4x4 per thread.
// AMODE: 0=plain(lda), 1=encoder token gather (row r -> emb_enc[token(b=r&63, t=r>>6)])
// EMODE: 0=+bias[n], 1=+addC[r*ldc+n], 2=raw
template <int AMODE, int EMODE>
__global__ void __launch_bounds__(256) k_gemm64(
    const float* __restrict__ A, int lda,
    const float* __restrict__ W, int ldw,
    const float* __restrict__ bias,
    const float* __restrict__ addC, int ldc,
    float* __restrict__ out, int ldo,
    int N, int K,
    const int* __restrict__ tok32, const float* __restrict__ emb) {
    __shared__ float As[16][68];
    __shared__ float Bs[16][68];
    const int tid = threadIdx.x;
    const int lrow = tid >> 2;
    const int kq = (tid & 3) << 2;
    const int bm = blockIdx.y << 6;
    const int bn = blockIdx.x << 6;

    const float* arow;
    {
        int gm = bm + lrow;
        if (AMODE == 1) {
            int b = gm & 63, t = gm >> 6;
            int idx = b * Sz + t;
            int token = g_is64[0] ? tok32[2 * idx] : tok32[idx];
            arow = emb + (size_t)token * Hz;
        } else {
            arow = A + (size_t)gm * lda;
        }
    }
    const int gn = bn + lrow;
    const float* wrow = W + (size_t)gn * ldw;
    const bool wok = (gn < N);

    float acc[4][4];
#pragma unroll
    for (int i = 0; i < 4; i++)
#pragma unroll
        for (int j = 0; j < 4; j++) acc[i][j] = 0.0f;

    const int ty = tid >> 4, tx = tid & 15;

    for (int k0 = 0; k0 < K; k0 += 16) {
        float4 av = *(const float4*)(arow + k0 + kq);
        float4 wv = make_float4(0.f, 0.f, 0.f, 0.f);
        if (wok) wv = *(const float4*)(wrow + k0 + kq);
        __syncthreads();
        As[kq + 0][lrow] = av.x; As[kq + 1][lrow] = av.y; As[kq + 2][lrow] = av.z; As[kq + 3][lrow] = av.w;
        Bs[kq + 0][lrow] = wv.x; Bs[kq + 1][lrow] = wv.y; Bs[kq + 2][lrow] = wv.z; Bs[kq + 3][lrow] = wv.w;
        __syncthreads();
#pragma unroll
        for (int kk = 0; kk < 16; kk++) {
            float4 a = *(const float4*)(&As[kk][ty << 2]);
            float4 b = *(const float4*)(&Bs[kk][tx << 2]);
            acc[0][0] += a.x * b.x; acc[0][1] += a.x * b.y; acc[0][2] += a.x * b.z; acc[0][3] += a.x * b.w;
            acc[1][0] += a.y * b.x; acc[1][1] += a.y * b.y; acc[1][2] += a.y * b.z; acc[1][3] += a.y * b.w;
            acc[2][0] += a.z * b.x; acc[2][1] += a.z * b.y; acc[2][2] += a.z * b.z; acc[2][3] += a.z * b.w;
            acc[3][0] += a.w * b.x; acc[3][1] += a.w * b.y; acc[3][2] += a.w * b.z; acc[3][3] += a.w * b.w;
        }
    }
    const int om = bm + (ty << 2);
    const int on = bn + (tx << 2);
#pragma unroll
    for (int i = 0; i < 4; i++) {
        float* orow = out + (size_t)(om + i) * ldo;
        const float* crow = (EMODE == 1) ? (addC + (size_t)(om + i) * ldc) : (const float*)0;
#pragma unroll
        for (int j = 0; j < 4; j++) {
            int c = on + j;
            if (c < N) {
                float v = acc[i][j];
                if (EMODE == 0) v += bias[c];
                if (EMODE == 1) v += crow[c];
                orow[c] = v;
            }
        }
    }
}

// ---------------- narrow GEMM: M=64 fixed, BN=32, 128 threads --------------------
// (used only for s2 = hd @ Wd^T + bd)
__global__ void __launch_bounds__(128) k_gemm32(
    const float* __restrict__ A, int lda,
    const float* __restrict__ W, int ldw,
    const float* __restrict__ bias,
    float* __restrict__ out, int ldo,
    int N, int K) {
    __shared__ float As[16][68];
    __shared__ float Bs[16][36];
    const int tid = threadIdx.x;
    const int r0 = tid >> 2;         // 0..31
    const int r1 = r0 + 32;
    const int kq = (tid & 3) << 2;
    const int bn = blockIdx.x << 5;

    const float* arow0 = A + (size_t)r0 * lda;
    const float* arow1 = A + (size_t)r1 * lda;
    const float* wrow = W + (size_t)(bn + r0) * ldw;

    float acc[4][4];
#pragma unroll
    for (int i = 0; i < 4; i++)
#pragma unroll
        for (int j = 0; j < 4; j++) acc[i][j] = 0.0f;

    const int ty = tid >> 3;  // 0..15 (M)
    const int tx = tid & 7;   // 0..7  (N)

    for (int k0 = 0; k0 < K; k0 += 16) {
        float4 a0 = *(const float4*)(arow0 + k0 + kq);
        float4 a1 = *(const float4*)(arow1 + k0 + kq);
        float4 wv = *(const float4*)(wrow + k0 + kq);
        __syncthreads();
        As[kq + 0][r0] = a0.x; As[kq + 1][r0] = a0.y; As[kq + 2][r0] = a0.z; As[kq + 3][r0] = a0.w;
        As[kq + 0][r1] = a1.x; As[kq + 1][r1] = a1.y; As[kq + 2][r1] = a1.z; As[kq + 3][r1] = a1.w;
        Bs[kq + 0][r0] = wv.x; Bs[kq + 1][r0] = wv.y; Bs[kq + 2][r0] = wv.z; Bs[kq + 3][r0] = wv.w;
        __syncthreads();
#pragma unroll
        for (int kk = 0; kk < 16; kk++) {
            float4 a = *(const float4*)(&As[kk][ty << 2]);
            float4 b = *(const float4*)(&Bs[kk][tx << 2]);
            acc[0][0] += a.x * b.x; acc[0][1] += a.x * b.y; acc[0][2] += a.x * b.z; acc[0][3] += a.x * b.w;
            acc[1][0] += a.y * b.x; acc[1][1] += a.y * b.y; acc[1][2] += a.y * b.z; acc[1][3] += a.y * b.w;
            acc[2][0] += a.z * b.x; acc[2][1] += a.z * b.y; acc[2][2] += a.z * b.z; acc[2][3] += a.z * b.w;
            acc[3][0] += a.w * b.x; acc[3][1] += a.w * b.y; acc[3][2] += a.w * b.z; acc[3][3] += a.w * b.w;
        }
    }
    const int om = ty << 2;
    const int on = bn + (tx << 2);
#pragma unroll
    for (int i = 0; i < 4; i++) {
        float* orow = out + (size_t)(om + i) * ldo;
#pragma unroll
        for (int j = 0; j < 4; j++) {
            int c = on + j;
            if (c < N) orow[c] = acc[i][j] + bias[c];
        }
    }
}

// ---------------- fused encoder recurrence GEMM ----------------------------------
// grid (128, 2), 128 threads. blockIdx.y selects K-half (0: cols 0..511 -> g_gates
// with +Xg[t]; 1: cols 512..1023 -> g_gates2 raw). gates = h @ Whh_e^T (+ Xg).
__global__ void __launch_bounds__(128) k_enc_step(
    const float* __restrict__ Whh, const float* __restrict__ xg_t) {
    __shared__ float As[16][68];
    __shared__ float Bs[16][36];
    const int tid = threadIdx.x;
    const int r0 = tid >> 2;
    const int r1 = r0 + 32;
    const int kq = (tid & 3) << 2;
    const int bn = blockIdx.x << 5;
    const int half = blockIdx.y;
    const int ko = half << 9;  // 0 or 512

    const float* arow0 = g_h + (size_t)r0 * Hz + ko;
    const float* arow1 = g_h + (size_t)r1 * Hz + ko;
    const float* wrow = Whh + (size_t)(bn + r0) * Hz + ko;

    float acc[4][4];
#pragma unroll
    for (int i = 0; i < 4; i++)
#pragma unroll
        for (int j = 0; j < 4; j++) acc[i][j] = 0.0f;

    const int ty = tid >> 3;
    const int tx = tid & 7;

    for (int k0 = 0; k0 < 512; k0 += 16) {
        float4 a0 = *(const float4*)(arow0 + k0 + kq);
        float4 a1 = *(const float4*)(arow1 + k0 + kq);
        float4 wv = *(const float4*)(wrow + k0 + kq);
        __syncthreads();
        As[kq + 0][r0] = a0.x; As[kq + 1][r0] = a0.y; As[kq + 2][r0] = a0.z; As[kq + 3][r0] = a0.w;
        As[kq + 0][r1] = a1.x; As[kq + 1][r1] = a1.y; As[kq + 2][r1] = a1.z; As[kq + 3][r1] = a1.w;
        Bs[kq + 0][r0] = wv.x; Bs[kq + 1][r0] = wv.y; Bs[kq + 2][r0] = wv.z; Bs[kq + 3][r0] = wv.w;
        __syncthreads();
#pragma unroll
        for (int kk = 0; kk < 16; kk++) {
            float4 a = *(const float4*)(&As[kk][ty << 2]);
            float4 b = *(const float4*)(&Bs[kk][tx << 2]);
            acc[0][0] += a.x * b.x; acc[0][1] += a.x * b.y; acc[0][2] += a.x * b.z; acc[0][3] += a.x * b.w;
            acc[1][0] += a.y * b.x; acc[1][1] += a.y * b.y; acc[1][2] += a.y * b.z; acc[1][3] += a.y * b.w;
            acc[2][0] += a.z * b.x; acc[2][1] += a.z * b.y; acc[2][2] += a.z * b.z; acc[2][3] += a.z * b.w;
            acc[3][0] += a.w * b.x; acc[3][1] += a.w * b.y; acc[3][2] += a.w * b.z; acc[3][3] += a.w * b.w;
        }
    }
    const int om = ty << 2;
    const int on = bn + (tx << 2);
    float* outb = half ? g_gates2 : g_gates;
#pragma unroll
    for (int i = 0; i < 4; i++) {
        float* orow = outb + (size_t)(om + i) * G4;
        const float* crow = xg_t + (size_t)(om + i) * G4;
#pragma unroll
        for (int j = 0; j < 4; j++) {
            int c = on + j;
            float v = acc[i][j];
            if (half == 0) v += crow[c];
            orow[c] = v;
        }
    }
}

// ---------------- fused decoder input GEMM ---------------------------------------
// grid (128, 2), 128 threads. blockIdx.y=0: emb_dec[g_tok[b]] @ Wih_d[:, 0:H]^T
// + g_dconst -> g_gates.  blockIdx.y=1: ctx @ Wih_d[:, H:2H]^T -> g_gates2.
__global__ void __launch_bounds__(128) k_dec_step(
    const float* __restrict__ Wih, const float* __restrict__ emb) {
    __shared__ float As[16][68];
    __shared__ float Bs[16][36];
    const int tid = threadIdx.x;
    const int r0 = tid >> 2;
    const int r1 = r0 + 32;
    const int kq = (tid & 3) << 2;
    const int bn = blockIdx.x << 5;
    const int half = blockIdx.y;

    const float* arow0;
    const float* arow1;
    if (half == 0) {
        arow0 = emb + (size_t)g_tok[r0] * Hz;
        arow1 = emb + (size_t)g_tok[r1] * Hz;
    } else {
        arow0 = g_ctx + (size_t)r0 * Hz;
        arow1 = g_ctx + (size_t)r1 * Hz;
    }
    const float* wrow = Wih + (size_t)(bn + r0) * (2 * Hz) + (half ? Hz : 0);

    float acc[4][4];
#pragma unroll
    for (int i = 0; i < 4; i++)
#pragma unroll
        for (int j = 0; j < 4; j++) acc[i][j] = 0.0f;

    const int ty = tid >> 3;
    const int tx = tid & 7;

    for (int k0 = 0; k0 < Hz; k0 += 16) {
        float4 a0 = *(const float4*)(arow0 + k0 + kq);
        float4 a1 = *(const float4*)(arow1 + k0 + kq);
        float4 wv = *(const float4*)(wrow + k0 + kq);
        __syncthreads();
        As[kq + 0][r0] = a0.x; As[kq + 1][r0] = a0.y; As[kq + 2][r0] = a0.z; As[kq + 3][r0] = a0.w;
        As[kq + 0][r1] = a1.x; As[kq + 1][r1] = a1.y; As[kq + 2][r1] = a1.z; As[kq + 3][r1] = a1.w;
        Bs[kq + 0][r0] = wv.x; Bs[kq + 1][r0] = wv.y; Bs[kq + 2][r0] = wv.z; Bs[kq + 3][r0] = wv.w;
        __syncthreads();
#pragma unroll
        for (int kk = 0; kk < 16; kk++) {
            float4 a = *(const float4*)(&As[kk][ty << 2]);
            float4 b = *(const float4*)(&Bs[kk][tx << 2]);
            acc[0][0] += a.x * b.x; acc[0][1] += a.x * b.y; acc[0][2] += a.x * b.z; acc[0][3] += a.x * b.w;
            acc[1][0] += a.y * b.x; acc[1][1] += a.y * b.y; acc[1][2] += a.y * b.z; acc[1][3] += a.y * b.w;
            acc[2][0] += a.z * b.x; acc[2][1] += a.z * b.y; acc[2][2] += a.z * b.z; acc[2][3] += a.z * b.w;
            acc[3][0] += a.w * b.x; acc[3][1] += a.w * b.y; acc[3][2] += a.w * b.z; acc[3][3] += a.w * b.w;
        }
    }
    const int om = ty << 2;
    const int on = bn + (tx << 2);
    float* outb = half ? g_gates2 : g_gates;
#pragma unroll
    for (int i = 0; i < 4; i++) {
        float* orow = outb + (size_t)(om + i) * G4;
        const float* crow = g_dconst + (size_t)(om + i) * G4;
#pragma unroll
        for (int j = 0; j < 4; j++) {
            int c = on + j;
            float v = acc[i][j];
            if (half == 0) v += crow[c];
            orow[c] = v;
        }
    }
}

// ---------------- LSTM cells ------------------------------------------------------
__global__ void k_enc_cell(int t) {
    int i = blockIdx.x * blockDim.x + threadIdx.x;  // 0..65535
    int b = i >> 10, u = i & 1023;
    const float* g1 = g_gates + b * G4;
    const float* g2 = g_gates2 + b * G4;
    float ig = g1[u] + g2[u];
    float fg = g1[u + 1024] + g2[u + 1024];
    float gg = g1[u + 2048] + g2[u + 2048];
    float og = g1[u + 3072] + g2[u + 3072];
    float c = sigm(fg) * g_c[i] + sigm(ig) * tanhf(gg);
    float h = sigm(og) * tanhf(c);
    g_c[i] = c;
    g_h[i] = h;
    g_enc[(size_t)t * Bz * Hz + i] = h;
}

__global__ void k_dec_cell() {
    int i = blockIdx.x * blockDim.x + threadIdx.x;
    int b = i >> 10, u = i & 1023;
    const float* g1 = g_gates + b * G4;
    const float* g2 = g_gates2 + b * G4;
    float ig = g1[u] + g2[u];
    float fg = g1[u + 1024] + g2[u + 1024];
    float gg = g1[u + 2048] + g2[u + 2048];
    float og = g1[u + 3072] + g2[u + 3072];
    float c = sigm(fg) * g_c[i] + sigm(ig) * tanhf(gg);  // g_c holds cN (never overwritten in decode)
    g_hd[i] = sigm(og) * tanhf(c);
}

// ---------------- attention: scores + softmax + context, one block per batch row --
__global__ void __launch_bounds__(256) k_attn(const float* __restrict__ Wv, const float* __restrict__ bv) {
    int b = blockIdx.x;
    __shared__ float s2s[Az];
    __shared__ float sc[Sz];
    __shared__ float red[8];
    int tid = threadIdx.x;
    int w = tid >> 5, l = tid & 31;
    for (int a = tid; a < Az; a += 256) s2s[a] = g_s2[b * Az + a];
    __syncthreads();
    for (int s = w; s < Sz; s += 8) {
        const float* row = g_s1 + ((size_t)s * Bz + b) * Az;
        float acc = 0.0f;
        for (int a = l; a < Az; a += 32) acc += tanhf(row[a] + s2s[a]) * Wv[a];
        for (int o = 16; o; o >>= 1) acc += __shfl_xor_sync(0xffffffffu, acc, o);
        if (l == 0) sc[s] = acc + bv[0];
    }
    __syncthreads();
    float m = -3.402823e38f;
    if (tid < Sz) m = sc[tid];
    for (int o = 16; o; o >>= 1) m = fmaxf(m, __shfl_xor_sync(0xffffffffu, m, o));
    if (l == 0) red[w] = m;
    __syncthreads();
    m = fmaxf(fmaxf(fmaxf(red[0], red[1]), fmaxf(red[2], red[3])),
              fmaxf(fmaxf(red[4], red[5]), fmaxf(red[6], red[7])));
    __syncthreads();
    float part = 0.0f;
    if (tid < Sz) { float e = expf(sc[tid] - m); sc[tid] = e; part = e; }
    for (int o = 16; o; o >>= 1) part += __shfl_xor_sync(0xffffffffu, part, o);
    if (l == 0) red[w] = part;
    __syncthreads();
    float inv = 1.0f / (red[0] + red[1] + red[2] + red[3] + red[4] + red[5] + red[6] + red[7]);
    for (int u = tid; u < Hz; u += 256) {
        float acc = 0.0f;
        for (int s = 0; s < Sz; s++) acc += sc[s] * g_enc[((size_t)s * Bz + b) * Hz + u];
        g_ctx[b * Hz + u] = acc * inv;
    }
}

// ---------------- argmax (first-occurrence tie-break, matches jnp.argmax) ---------
__global__ void __launch_bounds__(256) k_argmax(const float* __restrict__ out, int t) {
    int b = blockIdx.x;
    const float* lg = out + (size_t)b * Tz * Vz + (size_t)t * Vz;
    int tid = threadIdx.x;
    float bm = -3.402823e38f;
    int bi = Vz;
    for (int v = tid; v < Vz; v += 256) {
        float x = lg[v];
        if (x > bm) { bm = x; bi = v; }
        else if (x == bm && v < bi) bi = v;
    }
    __shared__ float sv[256];
    __shared__ int si[256];
    sv[tid] = bm; si[tid] = bi;
    __syncthreads();
    for (int o = 128; o; o >>= 1) {
        if (tid < o) {
            if (sv[tid + o] > sv[tid] || (sv[tid + o] == sv[tid] && si[tid + o] < si[tid])) {
                sv[tid] = sv[tid + o]; si[tid] = si[tid + o];
            }
        }
        __syncthreads();
    }
    if (tid == 0) g_tok[b] = si[0];
}

// ---------------- host orchestration ---------------------------------------------
extern "C" void kernel_launch(void* const* d_in, const int* in_sizes, int n_in,
                              void* d_out, int out_size) {
    const int*   in_enc   = (const int*)d_in[0];
    const float* init_ctx = (const float*)d_in[1];
    const int*   in_dec   = (const int*)d_in[2];
    const float* emb_enc  = (const float*)d_in[3];
    const float* emb_dec  = (const float*)d_in[4];
    const float* Wih_e    = (const float*)d_in[5];
    const float* Whh_e    = (const float*)d_in[6];
    const float* bih_e    = (const float*)d_in[7];
    const float* bhh_e    = (const float*)d_in[8];
    const float* Wih_d    = (const float*)d_in[9];
    const float* Whh_d    = (const float*)d_in[10];
    const float* bih_d    = (const float*)d_in[11];
    const float* bhh_d    = (const float*)d_in[12];
    const float* We       = (const float*)d_in[13];
    const float* be       = (const float*)d_in[14];
    const float* Wd       = (const float*)d_in[15];
    const float* bd       = (const float*)d_in[16];
    const float* Wv       = (const float*)d_in[17];
    const float* bv       = (const float*)d_in[18];
    const float* Wout     = (const float*)d_in[19];
    const float* bout     = (const float*)d_in[20];
    float* out = (float*)d_out;

    float *pXg, *pEnc, *pS1, *pH, *pDconst, *pHd, *pS2, *pBe, *pBd;
    cudaGetSymbolAddress((void**)&pXg, g_Xg);
    cudaGetSymbolAddress((void**)&pEnc, g_enc);
    cudaGetSymbolAddress((void**)&pS1, g_s1);
    cudaGetSymbolAddress((void**)&pH, g_h);
    cudaGetSymbolAddress((void**)&pDconst, g_dconst);
    cudaGetSymbolAddress((void**)&pHd, g_hd);
    cudaGetSymbolAddress((void**)&pS2, g_s2);
    cudaGetSymbolAddress((void**)&pBe, g_be);
    cudaGetSymbolAddress((void**)&pBd, g_bd);

    k_detect<<<1, 256>>>(in_enc, in_dec);
    k_init<<<256, 256>>>(bih_e, bhh_e, bih_d, bhh_d, init_ctx, in_dec);

    // Encoder input GEMM (hoisted): Xg[t*B+b][:] = emb_enc[tok(b,t)] @ Wih_e^T + b_e
    {
        dim3 g(G4 / 64, (Sz * Bz) / 64);
        k_gemm64<1, 0><<<g, 256>>>(nullptr, 0, Wih_e, Hz, pBe, nullptr, 0,
                                   pXg, G4, G4, Hz, in_enc, emb_enc);
    }

    // Encoder recurrence: one fused GEMM launch (both K-halves) + cell per step
    for (int t = 0; t < Sz; t++) {
        k_enc_step<<<dim3(G4 / 32, 2), 128>>>(Whh_e, pXg + (size_t)t * Bz * G4);
        k_enc_cell<<<256, 256>>>(t);
    }

    // s1 = enc @ We^T + be   [S*B, A]
    {
        dim3 g(Az / 64, (Sz * Bz) / 64);
        k_gemm64<0, 0><<<g, 256>>>(pEnc, Hz, We, Hz, be, nullptr, 0,
                                   pS1, Az, Az, Hz, nullptr, nullptr);
    }
    // decoder constant gates: hN @ Whh_d^T + b_d
    {
        dim3 g(G4 / 64, 1);
        k_gemm64<0, 0><<<g, 256>>>(pH, Hz, Whh_d, Hz, pBd, nullptr, 0,
                                   pDconst, G4, G4, Hz, nullptr, nullptr);
    }

    // Autoregressive decoder
    for (int t = 0; t < Tz; t++) {
        k_dec_step<<<dim3(G4 / 32, 2), 128>>>(Wih_d, emb_dec);
        k_dec_cell<<<256, 256>>>();
        // s2 = hd @ Wd^T + bd
        k_gemm32<<<dim3(Az / 32, 1), 128>>>(pHd, Hz, Wd, Hz, bd, pS2, Az, Az, Hz);
        k_attn<<<Bz, 256>>>(Wv, bv);
        // logits = hd @ Wout^T + bout  -> out[b][t][:]
        {
            dim3 gl((Vz + 63) / 64, 1);
            k_gemm64<0, 0><<<gl, 256>>>(pHd, Hz, Wout, Hz, bout, nullptr, 0,
                                        out + (size_t)t * Vz, Tz * Vz, Vz, Hz,
                                        nullptr, nullptr);
        }
        k_argmax<<<Bz, 256>>>(out, t);
    }
}